// round 8
// baseline (speedup 1.0000x reference)
#include <cuda_runtime.h>
#include <cstdint>

// Resample2d (FlowNet2 bilinear warp), B=4, C=64, H=384, W=512.
//
// R7: smem-tiled gather, fixed pipeline.
//   Block = 64x16 outputs (256 threads, 4 px/thread).
//   Window = 28x80 input tile whose ORIGIN is clamped (shifted window), so the
//   fill is pure contiguous 16B cp.async (no per-element clamping, 4x fewer
//   LDGSTS ops than R4). 4-stage ring buffer: fill of channel c+4 overlaps the
//   gathers of c+1..c+3, hiding the full fill latency (R4 was only 1-deep).
//   An empty commit_group is issued every iteration so the pending-group count
//   is constant and wait_group<3> always means "fill for channel c is done".
//   Taps outside the window (|flow| beyond halo; ~1e-9 prob) use an exact
//   global-memory fallback.

static constexpr int B = 4;
static constexpr int C = 64;
static constexpr int H = 384;
static constexpr int W = 512;
static constexpr int HW = H * W;

static constexpr int TX = 64;
static constexpr int TY = 16;
static constexpr int HUP = 6;                 // halo rows above (nominal)
static constexpr int HL  = 8;                 // halo cols left (nominal)
static constexpr int TROWS = 28;              // 16 + 6 + 6
static constexpr int TCOLS = 80;              // 64 + 8 + 8
static constexpr int SST   = 84;              // smem row stride (floats)
static constexpr int SELEM = TROWS * SST;     // 2352 floats per stage
static constexpr int F4PROW = TCOLS / 4;      // 20 float4 per row
static constexpr int FILLU  = TROWS * F4PROW; // 560 float4 units
static constexpr int NS = 4;                  // pipeline stages

__device__ __forceinline__ int iclamp(int v, int lo, int hi) {
    return min(max(v, lo), hi);
}

__device__ __forceinline__ void cp_async16(uint32_t dst, const float* src) {
    asm volatile("cp.async.cg.shared.global [%0], [%1], 16;" :: "r"(dst), "l"(src));
}
__device__ __forceinline__ void cp_commit() {
    asm volatile("cp.async.commit_group;" ::: "memory");
}
template <int N>
__device__ __forceinline__ void cp_wait() {
    asm volatile("cp.async.wait_group %0;" :: "n"(N) : "memory");
}

__global__ __launch_bounds__(256, 5) void resample2d_kernel(
    const float* __restrict__ in1,
    const float* __restrict__ flow,
    float* __restrict__ out)
{
    __shared__ float tile[NS][SELEM];

    int tid = threadIdx.x;
    int xb = blockIdx.x * TX;
    int yb = blockIdx.y * TY;
    int bz = blockIdx.z;

    // Shifted (origin-clamped) window — fill stays contiguous & aligned.
    int wxs = iclamp(xb - HL,  0, W - TCOLS);
    int wys = iclamp(yb - HUP, 0, H - TROWS);

    int x  = xb + (tid & 63);
    int ry = tid >> 6;                 // 0..3

    // ---- fill unit precompute: up to 3 float4 units per thread ----
    int gsrc[3], soff[3];
    #pragma unroll
    for (int k = 0; k < 3; ++k) {
        int u = tid + k * 256;
        int r = u / F4PROW;
        int c4 = u - r * F4PROW;
        bool v = (u < FILLU);
        gsrc[k] = v ? ((wys + r) * W + wxs + c4 * 4) : 0;
        soff[k] = v ? (r * SST + c4 * 4) : -1;
    }
    uint32_t smbase = (uint32_t)__cvta_generic_to_shared(&tile[0][0]);

    // ---- per-pixel flow preamble (4 pixels per thread) ----
    float fa[4], fbw[4];
    unsigned pk0[4], pk1[4];
    int fbmask = 0;
    int opix0 = (yb + ry) * W + x;

    const float* fptr = flow + (size_t)bz * 2 * HW;
    #pragma unroll
    for (int p = 0; p < 4; ++p) {
        int y   = yb + ry + 4 * p;
        int pix = y * W + x;
        float dx = fptr[pix];
        float dy = fptr[HW + pix];

        float xf = (float)x + dx;
        float yf = (float)y + dy;
        float x0f = floorf(xf);
        float y0f = floorf(yf);
        fa[p]  = xf - x0f;
        fbw[p] = yf - y0f;

        int x0i = (int)x0f;
        int y0i = (int)y0f;
        int x0 = iclamp(x0i,     0, W - 1);
        int x1 = iclamp(x0i + 1, 0, W - 1);
        int y0 = iclamp(y0i,     0, H - 1);
        int y1 = iclamp(y0i + 1, 0, H - 1);

        int tc0 = x0 - wxs;
        int tc1 = x1 - wxs;
        int tr0 = y0 - wys;
        int tr1 = y1 - wys;

        bool ok = (tc0 >= 0) & (tc1 < TCOLS) & (tr0 >= 0) & (tr1 < TROWS);
        if (ok) {
            pk0[p] = (unsigned)(tr0 * SST + tc0) | ((unsigned)(tr0 * SST + tc1) << 16);
            pk1[p] = (unsigned)(tr1 * SST + tc0) | ((unsigned)(tr1 * SST + tc1) << 16);
        } else {
            fbmask |= 1 << p;
            pk0[p] = (unsigned)(y0 * W + x0);
            pk1[p] = (unsigned)(x1 - x0) | ((unsigned)(y1 - y0) << 1);
        }
    }

    const float* bin  = in1 + (size_t)bz * C * HW;
    float*       bout = out + (size_t)bz * C * HW;

    // ---- prologue: fill channels 0..NS-1 into stages 0..NS-1 ----
    #pragma unroll
    for (int s = 0; s < NS; ++s) {
        const float* src = bin + (size_t)s * HW;
        uint32_t db = smbase + (uint32_t)(s * SELEM * 4);
        #pragma unroll
        for (int k = 0; k < 3; ++k)
            if (soff[k] >= 0) cp_async16(db + soff[k] * 4, src + gsrc[k]);
        cp_commit();
    }

    for (int c = 0; c < C; ++c) {
        cp_wait<NS - 1>();         // fill for channel c has landed
        __syncthreads();

        const float* tl  = tile[c & (NS - 1)];
        const float* src = bin + (size_t)c * HW;
        float*       dst = bout + (size_t)c * HW;

        #pragma unroll
        for (int p = 0; p < 4; ++p) {
            float a  = fa[p];
            float bw = fbw[p];
            float w00 = (1.0f - a) * (1.0f - bw);
            float w10 = a * (1.0f - bw);
            float w01 = (1.0f - a) * bw;
            float w11 = a * bw;

            float res;
            if (!((fbmask >> p) & 1)) {
                int t00 = pk0[p] & 0xffff;
                int t10 = pk0[p] >> 16;
                int t01 = pk1[p] & 0xffff;
                int t11 = pk1[p] >> 16;
                res = w00 * tl[t00] + w10 * tl[t10]
                    + w01 * tl[t01] + w11 * tl[t11];
            } else {
                int g00 = (int)pk0[p];
                int dxi = pk1[p] & 1;
                int dyi = (pk1[p] >> 1) & 1;
                const float* gp = src + g00;
                res = w00 * __ldg(gp)
                    + w10 * __ldg(gp + dxi)
                    + w01 * __ldg(gp + dyi * W)
                    + w11 * __ldg(gp + dyi * W + dxi);
            }
            dst[opix0 + p * 4 * W] = res;
        }
        __syncthreads();           // all reads of this stage done before refill

        // refill this stage with channel c+NS (or commit an empty group to
        // keep the pending-group count constant for wait_group<NS-1>)
        if (c + NS < C) {
            const float* nsrc = bin + (size_t)(c + NS) * HW;
            uint32_t db = smbase + (uint32_t)((c & (NS - 1)) * SELEM * 4);
            #pragma unroll
            for (int k = 0; k < 3; ++k)
                if (soff[k] >= 0) cp_async16(db + soff[k] * 4, nsrc + gsrc[k]);
        }
        cp_commit();
    }
}

extern "C" void kernel_launch(void* const* d_in, const int* in_sizes, int n_in,
                              void* d_out, int out_size)
{
    const float* in1  = (const float*)d_in[0];
    const float* flow = (const float*)d_in[1];
    float*       out  = (float*)d_out;

    dim3 grid(W / TX, H / TY, B);   // 8 x 24 x 4 = 768 blocks
    resample2d_kernel<<<grid, 256>>>(in1, flow, out);
}

// round 9
// speedup vs baseline: 1.5516x; 1.5516x over previous
#include <cuda_runtime.h>

// Resample2d (FlowNet2 bilinear warp), fixed shape B=4, C=64, H=384, W=512.
//
// R8: direct gather kernel, TWO adjacent pixels per thread (lane l handles
// x=2l and x=2l+1). Each scalar gather instruction now spans 64 columns of
// the image instead of 32, so its L1 line count grows ~1.5x while serving
// 2x the outputs: ~22% fewer L1 wavefronts per output (the proven wall).
// Gathers stay scalar LDG.32 (wide loads charge per-lane footprint — R2/R5
// regression evidence); stores are one coalesced float2 per lane.

static constexpr int B = 4;
static constexpr int C = 64;
static constexpr int H = 384;
static constexpr int W = 512;
static constexpr int HW = H * W;
static constexpr int NPAIR = B * H * (W / 2);   // 393216 threads

__global__ __launch_bounds__(256) void resample2d_kernel(
    const float* __restrict__ in1,
    const float* __restrict__ flow,
    float* __restrict__ out)
{
    int idx = blockIdx.x * blockDim.x + threadIdx.x;
    if (idx >= NPAIR) return;

    int xp = (idx & 255) << 1;       // even x of the pair (W/2 = 256)
    int t  = idx >> 8;               // b*H + y
    int y  = t % H;
    int b  = t / H;

    int pix = y * W + xp;
    const float* fptr = flow + (size_t)b * 2 * HW;
    float2 dxy = __ldg((const float2*)(fptr + pix));        // dx for x, x+1
    float2 dyy = __ldg((const float2*)(fptr + HW + pix));   // dy for x, x+1

    // ---- per-pixel tap setup (both pixels) ----
    int   off[8];      // i00,i10,i01,i11 for pixel A then pixel B
    float wgt[8];
    #pragma unroll
    for (int p = 0; p < 2; ++p) {
        float dx = p ? dxy.y : dxy.x;
        float dy = p ? dyy.y : dyy.x;
        int   x  = xp + p;

        float xf = (float)x + dx;
        float yf = (float)y + dy;
        float x0f = floorf(xf);
        float y0f = floorf(yf);
        float a  = xf - x0f;
        float bw = yf - y0f;

        int x0i = (int)x0f;
        int y0i = (int)y0f;
        int x0 = min(max(x0i,     0), W - 1);
        int x1 = min(max(x0i + 1, 0), W - 1);
        int y0 = min(max(y0i,     0), H - 1);
        int y1 = min(max(y0i + 1, 0), H - 1);

        off[4 * p + 0] = y0 * W + x0;
        off[4 * p + 1] = y0 * W + x1;
        off[4 * p + 2] = y1 * W + x0;
        off[4 * p + 3] = y1 * W + x1;
        wgt[4 * p + 0] = (1.0f - a) * (1.0f - bw);
        wgt[4 * p + 1] = a * (1.0f - bw);
        wgt[4 * p + 2] = (1.0f - a) * bw;
        wgt[4 * p + 3] = a * bw;
    }

    const float* src = in1 + (size_t)b * C * HW;
    float*       dst = out + (size_t)b * C * HW + pix;

    #pragma unroll 4
    for (int c = 0; c < C; ++c) {
        float vA0 = __ldg(src + off[0]);
        float vA1 = __ldg(src + off[1]);
        float vA2 = __ldg(src + off[2]);
        float vA3 = __ldg(src + off[3]);
        float vB0 = __ldg(src + off[4]);
        float vB1 = __ldg(src + off[5]);
        float vB2 = __ldg(src + off[6]);
        float vB3 = __ldg(src + off[7]);

        float2 r;
        r.x = wgt[0] * vA0 + wgt[1] * vA1 + wgt[2] * vA2 + wgt[3] * vA3;
        r.y = wgt[4] * vB0 + wgt[5] * vB1 + wgt[6] * vB2 + wgt[7] * vB3;
        *(float2*)dst = r;

        src += HW;
        dst += HW;
    }
}

extern "C" void kernel_launch(void* const* d_in, const int* in_sizes, int n_in,
                              void* d_out, int out_size)
{
    const float* in1  = (const float*)d_in[0];
    const float* flow = (const float*)d_in[1];
    float*       out  = (float*)d_out;

    int threads = 256;
    int blocks = (NPAIR + threads - 1) / threads;   // 1536
    resample2d_kernel<<<blocks, threads>>>(in1, flow, out);
}